// round 11
// baseline (speedup 1.0000x reference)
#include <cuda_runtime.h>
#include <cuda_fp16.h>
#include <stdint.h>

#define EN    1024
#define ED    64
#define SP    32768
#define NPOS  131072
#define MARGIN 4e-4f

// screen smem (bytes): ebuf 2x16KB | norms 2x256B
#define EB(i)  ((i) * 16384)
#define SNB(i) (32768 + (i) * 256)
#define SMEM_BYTES 33280

__device__ float    g_norms[EN];
__device__ __half2  g_eh[EN * ED];     // e_k duplicated into both halves
__device__ uint2    g_top[NPOS];
__device__ unsigned g_flagcnt;
__device__ unsigned g_flaglist[NPOS];

__device__ __forceinline__ unsigned sptr(const void* p) {
    return (unsigned)__cvta_generic_to_shared(p);
}
#define CP16(d, s)  asm volatile("cp.async.cg.shared.global [%0], [%1], 16;" :: "r"(d), "l"(s) : "memory")
#define CP_COMMIT() asm volatile("cp.async.commit_group;" ::: "memory")
#define CP_WAIT0()  asm volatile("cp.async.wait_group 0;" ::: "memory")

// ---------------- K1: prep = norms + half-dup codebook + flag reset ----------------
__global__ __launch_bounds__(256) void vq_prep_kernel(const float* __restrict__ emb) {
    int j = blockIdx.x * 256 + threadIdx.x;
    if (j == 0) g_flagcnt = 0;
    if (j < EN) {
        const float4* row = (const float4*)(emb + j * ED);
        float s = 0.f;
#pragma unroll
        for (int k = 0; k < ED / 4; k++) {
            float4 v = row[k];
            s += v.x * v.x + v.y * v.y + v.z * v.z + v.w * v.w;
        }
        g_norms[j] = s;
        const float* e = emb + j * ED;
#pragma unroll
        for (int k = 0; k < ED; k++) {
            __half h = __float2half(e[k]);
            g_eh[j * ED + k] = __halves2half2(h, h);
        }
    }
}

// ---------------- K2: HFMA2 screen (2 positions/thread packed in half2 lanes) ----------------
__global__ __launch_bounds__(128, 3)
void vq_screen_kernel(const float* __restrict__ z) {
    extern __shared__ char smraw[];
    const unsigned sb = sptr(smraw);
    const int tid = threadIdx.x;

    const int p0 = blockIdx.x * 256 + tid;
    const int p1 = p0 + 128;
    const int b  = p0 >> 15;
    const int base0 = b * (ED * SP) + (p0 & (SP - 1));
    const int base1 = b * (ED * SP) + (p1 & (SP - 1));

    // prefetch chunk 0 (64 codes = 16KB) + its norms
    {
        const char* src = (const char*)g_eh;
        unsigned dst = sb + EB(0);
#pragma unroll
        for (int i = 0; i < 8; i++)
            CP16(dst + (tid + i * 128) * 16, src + (tid + i * 128) * 16);
        if (tid < 16)
            CP16(sb + SNB(0) + tid * 16, (const char*)g_norms + tid * 16);
        CP_COMMIT();
    }

    // x for both positions -> 64 half2 regs (.x = pos0, .y = pos1)
    __half2 xh[ED];
#pragma unroll
    for (int k = 0; k < ED; k++)
        xh[k] = __halves2half2(__float2half(z[base0 + k * SP]),
                               __float2half(z[base1 + k * SP]));

    float v1a = 3.4e38f, v2a = 3.4e38f, v3a = 3.4e38f;
    float v1b = 3.4e38f, v2b = 3.4e38f, v3b = 3.4e38f;
    int i1a = 0, i2a = 0, i1b = 0, i2b = 0;

    CP_WAIT0();
    __syncthreads();

#pragma unroll 1
    for (int c = 0; c < 16; c++) {
        if (c < 15) {
            const char* src = (const char*)(g_eh + (c + 1) * 64 * ED);
            unsigned dst = sb + EB((c + 1) & 1);
#pragma unroll
            for (int i = 0; i < 8; i++)
                CP16(dst + (tid + i * 128) * 16, src + (tid + i * 128) * 16);
            if (tid < 16)
                CP16(sb + SNB((c + 1) & 1) + tid * 16,
                     (const char*)(g_norms + (c + 1) * 64) + tid * 16);
            CP_COMMIT();
        }
        const float4* ebuf = (const float4*)(smraw + EB(c & 1));
        const float*  snrm = (const float*) (smraw + SNB(c & 1));
        const int cbase = c * 64;

#pragma unroll 2
        for (int j = 0; j < 64; j++) {
            const float4* er = ebuf + j * 16;          // 64 half2 = 16 float4
            __half2 a0 = __float2half2_rn(0.f), a1 = a0, a2 = a0, a3 = a0;
#pragma unroll
            for (int g = 0; g < 16; g++) {
                float4 t = er[g];                      // LDS.128 broadcast
                const __half2* h = (const __half2*)&t;
                a0 = __hfma2(xh[4 * g + 0], h[0], a0);
                a1 = __hfma2(xh[4 * g + 1], h[1], a1);
                a2 = __hfma2(xh[4 * g + 2], h[2], a2);
                a3 = __hfma2(xh[4 * g + 3], h[3], a3);
            }
            float2 f0 = __half22float2(a0), f1 = __half22float2(a1);
            float2 f2 = __half22float2(a2), f3 = __half22float2(a3);
            float dot0 = (f0.x + f1.x) + (f2.x + f3.x);
            float dot1 = (f0.y + f1.y) + (f2.y + f3.y);
            float en = snrm[j];
            float d0 = fmaf(-2.f, dot0, en);
            float d1 = fmaf(-2.f, dot1, en);
            int col = cbase + j;
            if (d0 < v1a)      { v3a = v2a; v2a = v1a; i2a = i1a; v1a = d0; i1a = col; }
            else if (d0 < v2a) { v3a = v2a; v2a = d0; i2a = col; }
            else if (d0 < v3a) { v3a = d0; }
            if (d1 < v1b)      { v3b = v2b; v2b = v1b; i2b = i1b; v1b = d1; i1b = col; }
            else if (d1 < v2b) { v3b = v2b; v2b = d1; i2b = col; }
            else if (d1 < v3b) { v3b = d1; }
        }
        if (c < 15) CP_WAIT0();
        __syncthreads();
    }

    unsigned f2a = (__fsub_rn(v2a, v1a) <= MARGIN) ? 0x80000000u : 0u;
    unsigned f2b = (__fsub_rn(v2b, v1b) <= MARGIN) ? 0x80000000u : 0u;
    g_top[p0] = make_uint2((unsigned)i1a | f2a, (unsigned)i2a);
    g_top[p1] = make_uint2((unsigned)i1b | f2b, (unsigned)i2b);
    if (__fsub_rn(v3a, v1a) <= MARGIN) g_flaglist[atomicAdd(&g_flagcnt, 1u)] = p0;
    if (__fsub_rn(v3b, v1b) <= MARGIN) g_flaglist[atomicAdd(&g_flagcnt, 1u)] = p1;
}

// ---------------- K3: finalize (exact reference-rounded top-2 rescore + scatter) ----------------
__global__ __launch_bounds__(256) void vq_finalize_kernel(const float* __restrict__ z,
                                                          const float* __restrict__ emb,
                                                          float* __restrict__ out) {
    int pos = blockIdx.x * 256 + threadIdx.x;
    uint2 t = g_top[pos];
    int i1 = (int)(t.x & 0x7FFFFFFFu), i2 = (int)t.y;
    int base = (pos >> 15) * (ED * SP) + (pos & (SP - 1));
    int idx = i1;
    if (t.x & 0x80000000u) {
        float xn = 0.f, d1 = 0.f, d2 = 0.f;
        const float* e1 = emb + i1 * ED;
        const float* e2 = emb + i2 * ED;
#pragma unroll
        for (int k = 0; k < ED; k++) {
            float x = z[base + k * SP];
            xn = __fadd_rn(xn, __fmul_rn(x, x));
            d1 = fmaf(x, e1[k], d1);
            d2 = fmaf(x, e2[k], d2);
        }
        float dd1 = __fsub_rn(__fadd_rn(xn, g_norms[i1]), __fmul_rn(2.0f, d1));
        float dd2 = __fsub_rn(__fadd_rn(xn, g_norms[i2]), __fmul_rn(2.0f, d2));
        if (dd2 < dd1 || (dd2 == dd1 && i2 < i1)) idx = i2;
    }
    const float4* er = (const float4*)(emb + idx * ED);
#pragma unroll
    for (int k = 0; k < ED / 4; k++) {
        float4 v = er[k];
        out[base + (4 * k + 0) * SP] = v.x;
        out[base + (4 * k + 1) * SP] = v.y;
        out[base + (4 * k + 2) * SP] = v.z;
        out[base + (4 * k + 3) * SP] = v.w;
    }
}

// ---------------- K4: full exact scan for flag3 positions (warp/position) ----------------
__global__ __launch_bounds__(128) void vq_fullscan_kernel(const float* __restrict__ z,
                                                          const float* __restrict__ emb,
                                                          float* __restrict__ out) {
    int w = (blockIdx.x * 128 + threadIdx.x) >> 5, lid = threadIdx.x & 31;
    int nw = gridDim.x * 4;
    unsigned cnt = g_flagcnt;
    for (unsigned f = w; f < cnt; f += nw) {
        int pos = g_flaglist[f];
        int base = (pos >> 15) * (ED * SP) + (pos & (SP - 1));
        float x[ED], xn = 0.f;
#pragma unroll
        for (int k = 0; k < ED; k++) {
            x[k] = z[base + k * SP];
            xn = __fadd_rn(xn, __fmul_rn(x[k], x[k]));
        }
        float best = 3.4e38f; int bi = EN;
        for (int c = lid; c < EN; c += 32) {
            const float* e = emb + c * ED;
            float dot = 0.f;
#pragma unroll
            for (int k = 0; k < ED; k++) dot = fmaf(x[k], e[k], dot);
            float d = __fsub_rn(__fadd_rn(xn, g_norms[c]), __fmul_rn(2.0f, dot));
            if (d < best) { best = d; bi = c; }
        }
        for (int o = 16; o; o >>= 1) {
            float ob = __shfl_down_sync(0xFFFFFFFFu, best, o);
            int   oi = __shfl_down_sync(0xFFFFFFFFu, bi, o);
            if (ob < best || (ob == best && oi < bi)) { best = ob; bi = oi; }
        }
        bi = __shfl_sync(0xFFFFFFFFu, bi, 0);
        for (int k = lid; k < ED; k += 32) out[base + k * SP] = emb[bi * ED + k];
    }
}

// ---------------- launcher ----------------
extern "C" void kernel_launch(void* const* d_in, const int* in_sizes, int n_in,
                              void* d_out, int out_size) {
    const float* z   = (const float*)d_in[0];
    const float* emb = (const float*)d_in[1];
    if (n_in >= 2 && in_sizes[0] == EN * ED && in_sizes[1] != EN * ED) {
        z = (const float*)d_in[1]; emb = (const float*)d_in[0];
    }
    float* out = (float*)d_out;

    cudaFuncSetAttribute(vq_screen_kernel,
                         cudaFuncAttributeMaxDynamicSharedMemorySize, SMEM_BYTES);
    vq_prep_kernel<<<4, 256>>>(emb);
    vq_screen_kernel<<<NPOS / 256, 128, SMEM_BYTES>>>(z);
    vq_finalize_kernel<<<NPOS / 256, 256>>>(z, emb, out);
    vq_fullscan_kernel<<<128, 128>>>(z, emb, out);
}

// round 12
// speedup vs baseline: 1.6376x; 1.6376x over previous
#include <cuda_runtime.h>
#include <cuda_fp16.h>
#include <stdint.h>

#define EN    1024
#define ED    64
#define SP    32768
#define NPOS  131072
#define MARGIN 4e-4f

// screen smem (bytes): ebuf 2x16KB | norms 2x256B
#define EB(i)  ((i) * 16384)
#define SNB(i) (32768 + (i) * 256)
#define SMEM_BYTES 33280

__device__ float    g_norms[EN];
__device__ __half2  g_eh[EN * ED];     // e_k duplicated into both halves
__device__ uint2    g_top[NPOS];
__device__ unsigned g_flagcnt;
__device__ unsigned g_flaglist[NPOS];

__device__ __forceinline__ unsigned sptr(const void* p) {
    return (unsigned)__cvta_generic_to_shared(p);
}
#define CP16(d, s)  asm volatile("cp.async.cg.shared.global [%0], [%1], 16;" :: "r"(d), "l"(s) : "memory")
#define CP_COMMIT() asm volatile("cp.async.commit_group;" ::: "memory")
#define CP_WAIT0()  asm volatile("cp.async.wait_group 0;" ::: "memory")

// ---------------- K1: prep = norms + half-dup codebook + flag reset ----------------
__global__ __launch_bounds__(256) void vq_prep_kernel(const float* __restrict__ emb) {
    int j = blockIdx.x * 256 + threadIdx.x;
    if (j == 0) g_flagcnt = 0;
    if (j < EN) {
        const float4* row = (const float4*)(emb + j * ED);
        float s = 0.f;
#pragma unroll
        for (int k = 0; k < ED / 4; k++) {
            float4 v = row[k];
            s += v.x * v.x + v.y * v.y + v.z * v.z + v.w * v.w;
        }
        g_norms[j] = s;
        const float* e = emb + j * ED;
#pragma unroll
        for (int k = 0; k < ED; k++) {
            __half h = __float2half(e[k]);
            g_eh[j * ED + k] = __halves2half2(h, h);
        }
    }
}

// ---------------- K2: HFMA2 screen (2 positions/thread packed in half2 lanes) ----------------
__global__ __launch_bounds__(128, 3)
void vq_screen_kernel(const float* __restrict__ z) {
    extern __shared__ char smraw[];
    const unsigned sb = sptr(smraw);
    const int tid = threadIdx.x;

    const int p0 = blockIdx.x * 256 + tid;
    const int p1 = p0 + 128;
    const int b  = p0 >> 15;
    const int base0 = b * (ED * SP) + (p0 & (SP - 1));
    const int base1 = b * (ED * SP) + (p1 & (SP - 1));

    // prefetch chunk 0 (64 codes = 16KB) + its norms
    {
        const char* src = (const char*)g_eh;
        unsigned dst = sb + EB(0);
#pragma unroll
        for (int i = 0; i < 8; i++)
            CP16(dst + (tid + i * 128) * 16, src + (tid + i * 128) * 16);
        if (tid < 16)
            CP16(sb + SNB(0) + tid * 16, (const char*)g_norms + tid * 16);
        CP_COMMIT();
    }

    // x for both positions -> 64 half2 regs (.x = pos0, .y = pos1)
    __half2 xh[ED];
#pragma unroll
    for (int k = 0; k < ED; k++)
        xh[k] = __halves2half2(__float2half(z[base0 + k * SP]),
                               __float2half(z[base1 + k * SP]));

    float v1a = 3.4e38f, v2a = 3.4e38f, v3a = 3.4e38f;
    float v1b = 3.4e38f, v2b = 3.4e38f, v3b = 3.4e38f;
    int i1a = 0, i2a = 0, i1b = 0, i2b = 0;

    CP_WAIT0();
    __syncthreads();

#pragma unroll 1
    for (int c = 0; c < 16; c++) {
        if (c < 15) {
            const char* src = (const char*)(g_eh + (c + 1) * 64 * ED);
            unsigned dst = sb + EB((c + 1) & 1);
#pragma unroll
            for (int i = 0; i < 8; i++)
                CP16(dst + (tid + i * 128) * 16, src + (tid + i * 128) * 16);
            if (tid < 16)
                CP16(sb + SNB((c + 1) & 1) + tid * 16,
                     (const char*)(g_norms + (c + 1) * 64) + tid * 16);
            CP_COMMIT();
        }
        const float4* ebuf = (const float4*)(smraw + EB(c & 1));
        const float*  snrm = (const float*) (smraw + SNB(c & 1));
        const int cbase = c * 64;

#pragma unroll 2
        for (int j = 0; j < 64; j++) {
            const float4* er = ebuf + j * 16;          // 64 half2 = 16 float4
            __half2 a0 = __float2half2_rn(0.f), a1 = a0, a2 = a0, a3 = a0;
#pragma unroll
            for (int g = 0; g < 16; g++) {
                float4 t = er[g];                      // LDS.128 broadcast
                const __half2* h = (const __half2*)&t;
                a0 = __hfma2(xh[4 * g + 0], h[0], a0);
                a1 = __hfma2(xh[4 * g + 1], h[1], a1);
                a2 = __hfma2(xh[4 * g + 2], h[2], a2);
                a3 = __hfma2(xh[4 * g + 3], h[3], a3);
            }
            float2 f0 = __half22float2(a0), f1 = __half22float2(a1);
            float2 f2 = __half22float2(a2), f3 = __half22float2(a3);
            float dot0 = (f0.x + f1.x) + (f2.x + f3.x);
            float dot1 = (f0.y + f1.y) + (f2.y + f3.y);
            float en = snrm[j];
            float d0 = fmaf(-2.f, dot0, en);
            float d1 = fmaf(-2.f, dot1, en);
            int col = cbase + j;
            if (d0 < v1a)      { v3a = v2a; v2a = v1a; i2a = i1a; v1a = d0; i1a = col; }
            else if (d0 < v2a) { v3a = v2a; v2a = d0; i2a = col; }
            else if (d0 < v3a) { v3a = d0; }
            if (d1 < v1b)      { v3b = v2b; v2b = v1b; i2b = i1b; v1b = d1; i1b = col; }
            else if (d1 < v2b) { v3b = v2b; v2b = d1; i2b = col; }
            else if (d1 < v3b) { v3b = d1; }
        }
        if (c < 15) CP_WAIT0();
        __syncthreads();
    }

    unsigned f2a = (__fsub_rn(v2a, v1a) <= MARGIN) ? 0x80000000u : 0u;
    unsigned f2b = (__fsub_rn(v2b, v1b) <= MARGIN) ? 0x80000000u : 0u;
    g_top[p0] = make_uint2((unsigned)i1a | f2a, (unsigned)i2a);
    g_top[p1] = make_uint2((unsigned)i1b | f2b, (unsigned)i2b);
    if (__fsub_rn(v3a, v1a) <= MARGIN) g_flaglist[atomicAdd(&g_flagcnt, 1u)] = p0;
    if (__fsub_rn(v3b, v1b) <= MARGIN) g_flaglist[atomicAdd(&g_flagcnt, 1u)] = p1;
}

// ---------------- K3: finalize (exact reference-rounded top-2 rescore + scatter) ----------------
__global__ __launch_bounds__(256) void vq_finalize_kernel(const float* __restrict__ z,
                                                          const float* __restrict__ emb,
                                                          float* __restrict__ out) {
    int pos = blockIdx.x * 256 + threadIdx.x;
    uint2 t = g_top[pos];
    int i1 = (int)(t.x & 0x7FFFFFFFu), i2 = (int)t.y;
    int base = (pos >> 15) * (ED * SP) + (pos & (SP - 1));
    int idx = i1;
    if (t.x & 0x80000000u) {
        float xn = 0.f, d1 = 0.f, d2 = 0.f;
        const float* e1 = emb + i1 * ED;
        const float* e2 = emb + i2 * ED;
#pragma unroll
        for (int k = 0; k < ED; k++) {
            float x = z[base + k * SP];
            xn = __fadd_rn(xn, __fmul_rn(x, x));
            d1 = fmaf(x, e1[k], d1);
            d2 = fmaf(x, e2[k], d2);
        }
        float dd1 = __fsub_rn(__fadd_rn(xn, g_norms[i1]), __fmul_rn(2.0f, d1));
        float dd2 = __fsub_rn(__fadd_rn(xn, g_norms[i2]), __fmul_rn(2.0f, d2));
        if (dd2 < dd1 || (dd2 == dd1 && i2 < i1)) idx = i2;
    }
    const float4* er = (const float4*)(emb + idx * ED);
#pragma unroll
    for (int k = 0; k < ED / 4; k++) {
        float4 v = er[k];
        out[base + (4 * k + 0) * SP] = v.x;
        out[base + (4 * k + 1) * SP] = v.y;
        out[base + (4 * k + 2) * SP] = v.z;
        out[base + (4 * k + 3) * SP] = v.w;
    }
}

// ---------------- K4: full exact scan for flag3 positions (warp/position) ----------------
__global__ __launch_bounds__(128) void vq_fullscan_kernel(const float* __restrict__ z,
                                                          const float* __restrict__ emb,
                                                          float* __restrict__ out) {
    int w = (blockIdx.x * 128 + threadIdx.x) >> 5, lid = threadIdx.x & 31;
    int nw = gridDim.x * 4;
    unsigned cnt = g_flagcnt;
    for (unsigned f = w; f < cnt; f += nw) {
        int pos = g_flaglist[f];
        int base = (pos >> 15) * (ED * SP) + (pos & (SP - 1));
        float x[ED], xn = 0.f;
#pragma unroll
        for (int k = 0; k < ED; k++) {
            x[k] = z[base + k * SP];
            xn = __fadd_rn(xn, __fmul_rn(x[k], x[k]));
        }
        float best = 3.4e38f; int bi = EN;
        for (int c = lid; c < EN; c += 32) {
            const float* e = emb + c * ED;
            float dot = 0.f;
#pragma unroll
            for (int k = 0; k < ED; k++) dot = fmaf(x[k], e[k], dot);
            float d = __fsub_rn(__fadd_rn(xn, g_norms[c]), __fmul_rn(2.0f, dot));
            if (d < best) { best = d; bi = c; }
        }
        for (int o = 16; o; o >>= 1) {
            float ob = __shfl_down_sync(0xFFFFFFFFu, best, o);
            int   oi = __shfl_down_sync(0xFFFFFFFFu, bi, o);
            if (ob < best || (ob == best && oi < bi)) { best = ob; bi = oi; }
        }
        bi = __shfl_sync(0xFFFFFFFFu, bi, 0);
        for (int k = lid; k < ED; k += 32) out[base + k * SP] = emb[bi * ED + k];
    }
}

// ---------------- launcher ----------------
extern "C" void kernel_launch(void* const* d_in, const int* in_sizes, int n_in,
                              void* d_out, int out_size) {
    const float* z   = (const float*)d_in[0];
    const float* emb = (const float*)d_in[1];
    if (n_in >= 2 && in_sizes[0] == EN * ED && in_sizes[1] != EN * ED) {
        z = (const float*)d_in[1]; emb = (const float*)d_in[0];
    }
    float* out = (float*)d_out;

    cudaFuncSetAttribute(vq_screen_kernel,
                         cudaFuncAttributeMaxDynamicSharedMemorySize, SMEM_BYTES);
    vq_prep_kernel<<<4, 256>>>(emb);
    vq_screen_kernel<<<NPOS / 256, 128, SMEM_BYTES>>>(z);
    vq_finalize_kernel<<<NPOS / 256, 256>>>(z, emb, out);
    vq_fullscan_kernel<<<128, 128>>>(z, emb, out);
}

// round 13
// speedup vs baseline: 1.6408x; 1.0020x over previous
#include <cuda_runtime.h>
#include <cuda_fp16.h>
#include <stdint.h>

#define EN    1024
#define ED    64
#define SP    32768
#define NPOS  131072
#define MARGIN 4e-4f

// screen smem (bytes): ebuf 2x16KB | norms 2x256B
#define EB(i)  ((i) * 16384)
#define SNB(i) (32768 + (i) * 256)
#define SMEM_BYTES 33280

__device__ float    g_norms[EN];
__device__ __half2  g_eh[EN * ED];     // e_k duplicated into both halves
__device__ uint2    g_top[NPOS];
__device__ unsigned g_flagcnt;
__device__ unsigned g_flaglist[NPOS];

__device__ __forceinline__ unsigned sptr(const void* p) {
    return (unsigned)__cvta_generic_to_shared(p);
}
#define CP16(d, s)  asm volatile("cp.async.cg.shared.global [%0], [%1], 16;" :: "r"(d), "l"(s) : "memory")
#define CP_COMMIT() asm volatile("cp.async.commit_group;" ::: "memory")
#define CP_WAIT0()  asm volatile("cp.async.wait_group 0;" ::: "memory")

// ---------------- K1: prep = norms + half-dup codebook + flag reset ----------------
__global__ __launch_bounds__(256) void vq_prep_kernel(const float* __restrict__ emb) {
    int j = blockIdx.x * 256 + threadIdx.x;
    if (j == 0) g_flagcnt = 0;
    if (j < EN) {
        const float4* row = (const float4*)(emb + j * ED);
        float s = 0.f;
#pragma unroll
        for (int k = 0; k < ED / 4; k++) {
            float4 v = row[k];
            s += v.x * v.x + v.y * v.y + v.z * v.z + v.w * v.w;
        }
        g_norms[j] = s;
        const float* e = emb + j * ED;
#pragma unroll
        for (int k = 0; k < ED; k++) {
            __half h = __float2half(e[k]);
            g_eh[j * ED + k] = __halves2half2(h, h);
        }
    }
}

// ---------------- K2: HFMA2 screen (2 positions/thread packed in half2 lanes) ----------------
__global__ __launch_bounds__(128, 3)
void vq_screen_kernel(const float* __restrict__ z) {
    extern __shared__ char smraw[];
    const unsigned sb = sptr(smraw);
    const int tid = threadIdx.x;

    const int p0 = blockIdx.x * 256 + tid;
    const int p1 = p0 + 128;
    const int b  = p0 >> 15;
    const int base0 = b * (ED * SP) + (p0 & (SP - 1));
    const int base1 = b * (ED * SP) + (p1 & (SP - 1));

    // prefetch chunk 0 (64 codes = 16KB) + its norms
    {
        const char* src = (const char*)g_eh;
        unsigned dst = sb + EB(0);
#pragma unroll
        for (int i = 0; i < 8; i++)
            CP16(dst + (tid + i * 128) * 16, src + (tid + i * 128) * 16);
        if (tid < 16)
            CP16(sb + SNB(0) + tid * 16, (const char*)g_norms + tid * 16);
        CP_COMMIT();
    }

    // x for both positions -> 64 half2 regs (.x = pos0, .y = pos1)
    __half2 xh[ED];
#pragma unroll
    for (int k = 0; k < ED; k++)
        xh[k] = __halves2half2(__float2half(z[base0 + k * SP]),
                               __float2half(z[base1 + k * SP]));

    float v1a = 3.4e38f, v2a = 3.4e38f, v3a = 3.4e38f;
    float v1b = 3.4e38f, v2b = 3.4e38f, v3b = 3.4e38f;
    int i1a = 0, i2a = 0, i1b = 0, i2b = 0;

    CP_WAIT0();
    __syncthreads();

#pragma unroll 1
    for (int c = 0; c < 16; c++) {
        if (c < 15) {
            const char* src = (const char*)(g_eh + (c + 1) * 64 * ED);
            unsigned dst = sb + EB((c + 1) & 1);
#pragma unroll
            for (int i = 0; i < 8; i++)
                CP16(dst + (tid + i * 128) * 16, src + (tid + i * 128) * 16);
            if (tid < 16)
                CP16(sb + SNB((c + 1) & 1) + tid * 16,
                     (const char*)(g_norms + (c + 1) * 64) + tid * 16);
            CP_COMMIT();
        }
        const float4* ebuf = (const float4*)(smraw + EB(c & 1));
        const float*  snrm = (const float*) (smraw + SNB(c & 1));
        const int cbase = c * 64;

#pragma unroll 2
        for (int j = 0; j < 64; j++) {
            const float4* er = ebuf + j * 16;          // 64 half2 = 16 float4
            __half2 a0 = __float2half2_rn(0.f), a1 = a0, a2 = a0, a3 = a0;
#pragma unroll
            for (int g = 0; g < 16; g++) {
                float4 t = er[g];                      // LDS.128 broadcast
                const __half2* h = (const __half2*)&t;
                a0 = __hfma2(xh[4 * g + 0], h[0], a0);
                a1 = __hfma2(xh[4 * g + 1], h[1], a1);
                a2 = __hfma2(xh[4 * g + 2], h[2], a2);
                a3 = __hfma2(xh[4 * g + 3], h[3], a3);
            }
            float2 f0 = __half22float2(a0), f1 = __half22float2(a1);
            float2 f2 = __half22float2(a2), f3 = __half22float2(a3);
            float dot0 = (f0.x + f1.x) + (f2.x + f3.x);
            float dot1 = (f0.y + f1.y) + (f2.y + f3.y);
            float en = snrm[j];
            float d0 = fmaf(-2.f, dot0, en);
            float d1 = fmaf(-2.f, dot1, en);
            int col = cbase + j;
            if (d0 < v1a)      { v3a = v2a; v2a = v1a; i2a = i1a; v1a = d0; i1a = col; }
            else if (d0 < v2a) { v3a = v2a; v2a = d0; i2a = col; }
            else if (d0 < v3a) { v3a = d0; }
            if (d1 < v1b)      { v3b = v2b; v2b = v1b; i2b = i1b; v1b = d1; i1b = col; }
            else if (d1 < v2b) { v3b = v2b; v2b = d1; i2b = col; }
            else if (d1 < v3b) { v3b = d1; }
        }
        if (c < 15) CP_WAIT0();
        __syncthreads();
    }

    unsigned f2a = (__fsub_rn(v2a, v1a) <= MARGIN) ? 0x80000000u : 0u;
    unsigned f2b = (__fsub_rn(v2b, v1b) <= MARGIN) ? 0x80000000u : 0u;
    g_top[p0] = make_uint2((unsigned)i1a | f2a, (unsigned)i2a);
    g_top[p1] = make_uint2((unsigned)i1b | f2b, (unsigned)i2b);
    if (__fsub_rn(v3a, v1a) <= MARGIN) g_flaglist[atomicAdd(&g_flagcnt, 1u)] = p0;
    if (__fsub_rn(v3b, v1b) <= MARGIN) g_flaglist[atomicAdd(&g_flagcnt, 1u)] = p1;
}

// ---------------- K3: finalize (exact reference-rounded top-2 rescore + scatter) ----------------
__global__ __launch_bounds__(256) void vq_finalize_kernel(const float* __restrict__ z,
                                                          const float* __restrict__ emb,
                                                          float* __restrict__ out) {
    int pos = blockIdx.x * 256 + threadIdx.x;
    uint2 t = g_top[pos];
    int i1 = (int)(t.x & 0x7FFFFFFFu), i2 = (int)t.y;
    int base = (pos >> 15) * (ED * SP) + (pos & (SP - 1));
    int idx = i1;
    if (t.x & 0x80000000u) {
        float xn = 0.f, d1 = 0.f, d2 = 0.f;
        const float* e1 = emb + i1 * ED;
        const float* e2 = emb + i2 * ED;
#pragma unroll
        for (int k = 0; k < ED; k++) {
            float x = z[base + k * SP];
            xn = __fadd_rn(xn, __fmul_rn(x, x));
            d1 = fmaf(x, e1[k], d1);
            d2 = fmaf(x, e2[k], d2);
        }
        float dd1 = __fsub_rn(__fadd_rn(xn, g_norms[i1]), __fmul_rn(2.0f, d1));
        float dd2 = __fsub_rn(__fadd_rn(xn, g_norms[i2]), __fmul_rn(2.0f, d2));
        if (dd2 < dd1 || (dd2 == dd1 && i2 < i1)) idx = i2;
    }
    const float4* er = (const float4*)(emb + idx * ED);
#pragma unroll
    for (int k = 0; k < ED / 4; k++) {
        float4 v = er[k];
        out[base + (4 * k + 0) * SP] = v.x;
        out[base + (4 * k + 1) * SP] = v.y;
        out[base + (4 * k + 2) * SP] = v.z;
        out[base + (4 * k + 3) * SP] = v.w;
    }
}

// ---------------- K4: full exact scan for flag3 positions (warp/position) ----------------
__global__ __launch_bounds__(128) void vq_fullscan_kernel(const float* __restrict__ z,
                                                          const float* __restrict__ emb,
                                                          float* __restrict__ out) {
    int w = (blockIdx.x * 128 + threadIdx.x) >> 5, lid = threadIdx.x & 31;
    int nw = gridDim.x * 4;
    unsigned cnt = g_flagcnt;
    for (unsigned f = w; f < cnt; f += nw) {
        int pos = g_flaglist[f];
        int base = (pos >> 15) * (ED * SP) + (pos & (SP - 1));
        float x[ED], xn = 0.f;
#pragma unroll
        for (int k = 0; k < ED; k++) {
            x[k] = z[base + k * SP];
            xn = __fadd_rn(xn, __fmul_rn(x[k], x[k]));
        }
        float best = 3.4e38f; int bi = EN;
        for (int c = lid; c < EN; c += 32) {
            const float* e = emb + c * ED;
            float dot = 0.f;
#pragma unroll
            for (int k = 0; k < ED; k++) dot = fmaf(x[k], e[k], dot);
            float d = __fsub_rn(__fadd_rn(xn, g_norms[c]), __fmul_rn(2.0f, dot));
            if (d < best) { best = d; bi = c; }
        }
        for (int o = 16; o; o >>= 1) {
            float ob = __shfl_down_sync(0xFFFFFFFFu, best, o);
            int   oi = __shfl_down_sync(0xFFFFFFFFu, bi, o);
            if (ob < best || (ob == best && oi < bi)) { best = ob; bi = oi; }
        }
        bi = __shfl_sync(0xFFFFFFFFu, bi, 0);
        for (int k = lid; k < ED; k += 32) out[base + k * SP] = emb[bi * ED + k];
    }
}

// ---------------- launcher ----------------
extern "C" void kernel_launch(void* const* d_in, const int* in_sizes, int n_in,
                              void* d_out, int out_size) {
    const float* z   = (const float*)d_in[0];
    const float* emb = (const float*)d_in[1];
    if (n_in >= 2 && in_sizes[0] == EN * ED && in_sizes[1] != EN * ED) {
        z = (const float*)d_in[1]; emb = (const float*)d_in[0];
    }
    float* out = (float*)d_out;

    cudaFuncSetAttribute(vq_screen_kernel,
                         cudaFuncAttributeMaxDynamicSharedMemorySize, SMEM_BYTES);
    vq_prep_kernel<<<4, 256>>>(emb);
    vq_screen_kernel<<<NPOS / 256, 128, SMEM_BYTES>>>(z);
    vq_finalize_kernel<<<NPOS / 256, 256>>>(z, emb, out);
    vq_fullscan_kernel<<<128, 128>>>(z, emb, out);
}

// round 14
// speedup vs baseline: 1.6419x; 1.0006x over previous
#include <cuda_runtime.h>
#include <cuda_fp16.h>
#include <stdint.h>

#define EN    1024
#define ED    64
#define SP    32768
#define NPOS  131072
#define MARGIN 4e-4f

// screen smem (bytes): ebuf 2x16KB | norms 2x256B
#define EB(i)  ((i) * 16384)
#define SNB(i) (32768 + (i) * 256)
#define SMEM_BYTES 33280

__device__ float    g_norms[EN];
__device__ __half2  g_eh[EN * ED];     // e_k duplicated into both halves
__device__ uint2    g_top[NPOS];
__device__ unsigned g_flagcnt;
__device__ unsigned g_flaglist[NPOS];

__device__ __forceinline__ unsigned sptr(const void* p) {
    return (unsigned)__cvta_generic_to_shared(p);
}
#define CP16(d, s)  asm volatile("cp.async.cg.shared.global [%0], [%1], 16;" :: "r"(d), "l"(s) : "memory")
#define CP_COMMIT() asm volatile("cp.async.commit_group;" ::: "memory")
#define CP_WAIT0()  asm volatile("cp.async.wait_group 0;" ::: "memory")

// ---------------- K1: prep = norms + half-dup codebook + flag reset ----------------
__global__ __launch_bounds__(256) void vq_prep_kernel(const float* __restrict__ emb) {
    int j = blockIdx.x * 256 + threadIdx.x;
    if (j == 0) g_flagcnt = 0;
    if (j < EN) {
        const float4* row = (const float4*)(emb + j * ED);
        float s = 0.f;
#pragma unroll
        for (int k = 0; k < ED / 4; k++) {
            float4 v = row[k];
            s += v.x * v.x + v.y * v.y + v.z * v.z + v.w * v.w;
        }
        g_norms[j] = s;
        const float* e = emb + j * ED;
#pragma unroll
        for (int k = 0; k < ED; k++) {
            __half h = __float2half(e[k]);
            g_eh[j * ED + k] = __halves2half2(h, h);
        }
    }
}

// ---------------- K2: HFMA2 screen (2 positions/thread packed in half2 lanes) ----------------
__global__ __launch_bounds__(128, 3)
void vq_screen_kernel(const float* __restrict__ z) {
    extern __shared__ char smraw[];
    const unsigned sb = sptr(smraw);
    const int tid = threadIdx.x;

    const int p0 = blockIdx.x * 256 + tid;
    const int p1 = p0 + 128;
    const int b  = p0 >> 15;
    const int base0 = b * (ED * SP) + (p0 & (SP - 1));
    const int base1 = b * (ED * SP) + (p1 & (SP - 1));

    // prefetch chunk 0 (64 codes = 16KB) + its norms
    {
        const char* src = (const char*)g_eh;
        unsigned dst = sb + EB(0);
#pragma unroll
        for (int i = 0; i < 8; i++)
            CP16(dst + (tid + i * 128) * 16, src + (tid + i * 128) * 16);
        if (tid < 16)
            CP16(sb + SNB(0) + tid * 16, (const char*)g_norms + tid * 16);
        CP_COMMIT();
    }

    // x for both positions -> 64 half2 regs (.x = pos0, .y = pos1)
    __half2 xh[ED];
#pragma unroll
    for (int k = 0; k < ED; k++)
        xh[k] = __halves2half2(__float2half(z[base0 + k * SP]),
                               __float2half(z[base1 + k * SP]));

    float v1a = 3.4e38f, v2a = 3.4e38f, v3a = 3.4e38f;
    float v1b = 3.4e38f, v2b = 3.4e38f, v3b = 3.4e38f;
    int i1a = 0, i2a = 0, i1b = 0, i2b = 0;

    CP_WAIT0();
    __syncthreads();

#pragma unroll 1
    for (int c = 0; c < 16; c++) {
        if (c < 15) {
            const char* src = (const char*)(g_eh + (c + 1) * 64 * ED);
            unsigned dst = sb + EB((c + 1) & 1);
#pragma unroll
            for (int i = 0; i < 8; i++)
                CP16(dst + (tid + i * 128) * 16, src + (tid + i * 128) * 16);
            if (tid < 16)
                CP16(sb + SNB((c + 1) & 1) + tid * 16,
                     (const char*)(g_norms + (c + 1) * 64) + tid * 16);
            CP_COMMIT();
        }
        const float4* ebuf = (const float4*)(smraw + EB(c & 1));
        const float*  snrm = (const float*) (smraw + SNB(c & 1));
        const int cbase = c * 64;

#pragma unroll 2
        for (int j = 0; j < 64; j++) {
            const float4* er = ebuf + j * 16;          // 64 half2 = 16 float4
            __half2 a0 = __float2half2_rn(0.f), a1 = a0, a2 = a0, a3 = a0;
#pragma unroll
            for (int g = 0; g < 16; g++) {
                float4 t = er[g];                      // LDS.128 broadcast
                const __half2* h = (const __half2*)&t;
                a0 = __hfma2(xh[4 * g + 0], h[0], a0);
                a1 = __hfma2(xh[4 * g + 1], h[1], a1);
                a2 = __hfma2(xh[4 * g + 2], h[2], a2);
                a3 = __hfma2(xh[4 * g + 3], h[3], a3);
            }
            float2 f0 = __half22float2(a0), f1 = __half22float2(a1);
            float2 f2 = __half22float2(a2), f3 = __half22float2(a3);
            float dot0 = (f0.x + f1.x) + (f2.x + f3.x);
            float dot1 = (f0.y + f1.y) + (f2.y + f3.y);
            float en = snrm[j];
            float d0 = fmaf(-2.f, dot0, en);
            float d1 = fmaf(-2.f, dot1, en);
            int col = cbase + j;
            if (d0 < v1a)      { v3a = v2a; v2a = v1a; i2a = i1a; v1a = d0; i1a = col; }
            else if (d0 < v2a) { v3a = v2a; v2a = d0; i2a = col; }
            else if (d0 < v3a) { v3a = d0; }
            if (d1 < v1b)      { v3b = v2b; v2b = v1b; i2b = i1b; v1b = d1; i1b = col; }
            else if (d1 < v2b) { v3b = v2b; v2b = d1; i2b = col; }
            else if (d1 < v3b) { v3b = d1; }
        }
        if (c < 15) CP_WAIT0();
        __syncthreads();
    }

    unsigned f2a = (__fsub_rn(v2a, v1a) <= MARGIN) ? 0x80000000u : 0u;
    unsigned f2b = (__fsub_rn(v2b, v1b) <= MARGIN) ? 0x80000000u : 0u;
    g_top[p0] = make_uint2((unsigned)i1a | f2a, (unsigned)i2a);
    g_top[p1] = make_uint2((unsigned)i1b | f2b, (unsigned)i2b);
    if (__fsub_rn(v3a, v1a) <= MARGIN) g_flaglist[atomicAdd(&g_flagcnt, 1u)] = p0;
    if (__fsub_rn(v3b, v1b) <= MARGIN) g_flaglist[atomicAdd(&g_flagcnt, 1u)] = p1;
}

// ---------------- K3: finalize (exact reference-rounded top-2 rescore + scatter) ----------------
__global__ __launch_bounds__(256) void vq_finalize_kernel(const float* __restrict__ z,
                                                          const float* __restrict__ emb,
                                                          float* __restrict__ out) {
    int pos = blockIdx.x * 256 + threadIdx.x;
    uint2 t = g_top[pos];
    int i1 = (int)(t.x & 0x7FFFFFFFu), i2 = (int)t.y;
    int base = (pos >> 15) * (ED * SP) + (pos & (SP - 1));
    int idx = i1;
    if (t.x & 0x80000000u) {
        float xn = 0.f, d1 = 0.f, d2 = 0.f;
        const float* e1 = emb + i1 * ED;
        const float* e2 = emb + i2 * ED;
#pragma unroll
        for (int k = 0; k < ED; k++) {
            float x = z[base + k * SP];
            xn = __fadd_rn(xn, __fmul_rn(x, x));
            d1 = fmaf(x, e1[k], d1);
            d2 = fmaf(x, e2[k], d2);
        }
        float dd1 = __fsub_rn(__fadd_rn(xn, g_norms[i1]), __fmul_rn(2.0f, d1));
        float dd2 = __fsub_rn(__fadd_rn(xn, g_norms[i2]), __fmul_rn(2.0f, d2));
        if (dd2 < dd1 || (dd2 == dd1 && i2 < i1)) idx = i2;
    }
    const float4* er = (const float4*)(emb + idx * ED);
#pragma unroll
    for (int k = 0; k < ED / 4; k++) {
        float4 v = er[k];
        out[base + (4 * k + 0) * SP] = v.x;
        out[base + (4 * k + 1) * SP] = v.y;
        out[base + (4 * k + 2) * SP] = v.z;
        out[base + (4 * k + 3) * SP] = v.w;
    }
}

// ---------------- K4: full exact scan for flag3 positions (warp/position) ----------------
__global__ __launch_bounds__(128) void vq_fullscan_kernel(const float* __restrict__ z,
                                                          const float* __restrict__ emb,
                                                          float* __restrict__ out) {
    int w = (blockIdx.x * 128 + threadIdx.x) >> 5, lid = threadIdx.x & 31;
    int nw = gridDim.x * 4;
    unsigned cnt = g_flagcnt;
    for (unsigned f = w; f < cnt; f += nw) {
        int pos = g_flaglist[f];
        int base = (pos >> 15) * (ED * SP) + (pos & (SP - 1));
        float x[ED], xn = 0.f;
#pragma unroll
        for (int k = 0; k < ED; k++) {
            x[k] = z[base + k * SP];
            xn = __fadd_rn(xn, __fmul_rn(x[k], x[k]));
        }
        float best = 3.4e38f; int bi = EN;
        for (int c = lid; c < EN; c += 32) {
            const float* e = emb + c * ED;
            float dot = 0.f;
#pragma unroll
            for (int k = 0; k < ED; k++) dot = fmaf(x[k], e[k], dot);
            float d = __fsub_rn(__fadd_rn(xn, g_norms[c]), __fmul_rn(2.0f, dot));
            if (d < best) { best = d; bi = c; }
        }
        for (int o = 16; o; o >>= 1) {
            float ob = __shfl_down_sync(0xFFFFFFFFu, best, o);
            int   oi = __shfl_down_sync(0xFFFFFFFFu, bi, o);
            if (ob < best || (ob == best && oi < bi)) { best = ob; bi = oi; }
        }
        bi = __shfl_sync(0xFFFFFFFFu, bi, 0);
        for (int k = lid; k < ED; k += 32) out[base + k * SP] = emb[bi * ED + k];
    }
}

// ---------------- launcher ----------------
extern "C" void kernel_launch(void* const* d_in, const int* in_sizes, int n_in,
                              void* d_out, int out_size) {
    const float* z   = (const float*)d_in[0];
    const float* emb = (const float*)d_in[1];
    if (n_in >= 2 && in_sizes[0] == EN * ED && in_sizes[1] != EN * ED) {
        z = (const float*)d_in[1]; emb = (const float*)d_in[0];
    }
    float* out = (float*)d_out;

    cudaFuncSetAttribute(vq_screen_kernel,
                         cudaFuncAttributeMaxDynamicSharedMemorySize, SMEM_BYTES);
    vq_prep_kernel<<<4, 256>>>(emb);
    vq_screen_kernel<<<NPOS / 256, 128, SMEM_BYTES>>>(z);
    vq_finalize_kernel<<<NPOS / 256, 256>>>(z, emb, out);
    vq_fullscan_kernel<<<128, 128>>>(z, emb, out);
}